// round 8
// baseline (speedup 1.0000x reference)
#include <cuda_runtime.h>
#include <cuda_bf16.h>
#include <math.h>

#define MAXN 100000
#define MAXE 1600000
#define MAXET (MAXN + MAXE)

#define NEG_ATT 0.2f
#define NEG_ACT 0.01f

// ---------------- scratch ----------------
__device__ __nv_bfloat16 g_h1b[MAXN * 128];
__device__ float g_as1[MAXN * 8];
__device__ float g_ad1[MAXN * 8];
__device__ float g_h2[MAXN * 16];
__device__ float g_as2[MAXN];
__device__ float g_ad2[MAXN];
__device__ int   g_deg[MAXN];      // zero at load; re-zeroed by k_csr each call
__device__ int   g_rs[MAXN + 1];
__device__ int   g_cur[MAXN];
__device__ int   g_esrc[MAXET];
// decoupled-lookback state (zero at load; reset by k_scatter each call)
__device__ volatile int g_flag[256];
__device__ int g_aggval[256];
__device__ int g_prefval[256];

// ---------------- f32x2 helpers ----------------
__device__ __forceinline__ unsigned long long ffma2(unsigned long long a,
                                                    unsigned long long b,
                                                    unsigned long long c) {
    unsigned long long d;
    asm("fma.rn.f32x2 %0, %1, %2, %3;" : "=l"(d) : "l"(a), "l"(b), "l"(c));
    return d;
}
__device__ __forceinline__ unsigned long long pack2(float a, float b) {
    unsigned long long r;
    asm("mov.b64 %0, {%1, %2};" : "=l"(r) : "f"(a), "f"(b));
    return r;
}
__device__ __forceinline__ float2 unpack2(unsigned long long v) {
    float2 r;
    asm("mov.b64 {%0, %1}, %2;" : "=f"(r.x), "=f"(r.y) : "l"(v));
    return r;
}

// ---------------- fat kernel: GEMM1 (FFMA2) + fused alpha1  ||  hist ----------------
#define HIST_B 512
__global__ void k_fat(const float* __restrict__ x, const float* __restrict__ W,
                      const float* __restrict__ a1s, const float* __restrict__ a1d,
                      const int* __restrict__ dst, int N, int E, int GB) {
    if (blockIdx.x >= GB) {
        int b = blockIdx.x - GB;
        for (int e = b * 128 + threadIdx.x; e < E; e += 128 * HIST_B)
            atomicAdd(&g_deg[dst[e]], 1);
        return;
    }
    __shared__ float xs[32 * 128];
    int t = threadIdx.x;
    int n0 = blockIdx.x * 32;
    const float4* x4 = (const float4*)x;
    float4* xs4 = (float4*)xs;
    for (int i = t; i < 32 * 32; i += 128) {
        int row = i >> 5, c4 = i & 31;
        float4 v = make_float4(0.f, 0.f, 0.f, 0.f);
        if (n0 + row < N) v = x4[(size_t)(n0 + row) * 32 + c4];
        xs4[i] = v;
    }
    __syncthreads();

    unsigned long long acc2[32];
#pragma unroll
    for (int i = 0; i < 32; i++) acc2[i] = 0ULL;

    const ulonglong2* xsp = (const ulonglong2*)xs;
    for (int kq = 0; kq < 32; kq++) {
        int k = kq * 4;
        float w0 = __ldg(&W[(k + 0) * 128 + t]);
        float w1 = __ldg(&W[(k + 1) * 128 + t]);
        float w2 = __ldg(&W[(k + 2) * 128 + t]);
        float w3 = __ldg(&W[(k + 3) * 128 + t]);
        unsigned long long wp0 = pack2(w0, w1);
        unsigned long long wp1 = pack2(w2, w3);
#pragma unroll
        for (int nl = 0; nl < 32; nl++) {
            ulonglong2 xv = xsp[nl * 32 + kq];
            acc2[nl] = ffma2(xv.x, wp0, acc2[nl]);
            acc2[nl] = ffma2(xv.y, wp1, acc2[nl]);
        }
    }

    float asv = __ldg(&a1s[t]);
    float adv = __ldg(&a1d[t]);
    int hh = t >> 4;
    int cc = t & 15;
    int l = t & 31;
#pragma unroll
    for (int nl = 0; nl < 32; nl++) {
        float2 p = unpack2(acc2[nl]);
        float h = p.x + p.y;
        float vs = h * asv;
        float vd = h * adv;
#pragma unroll
        for (int off = 8; off; off >>= 1) {
            vs += __shfl_xor_sync(0xFFFFFFFFu, vs, off);
            vd += __shfl_xor_sync(0xFFFFFFFFu, vd, off);
        }
        float hn = __shfl_down_sync(0xFFFFFFFFu, h, 1);
        int n = n0 + nl;
        if (n < N) {
            if ((l & 1) == 0) {
                __nv_bfloat162 bv = __floats2bfloat162_rn(h, hn);
                ((__nv_bfloat162*)(g_h1b + (size_t)n * 128))[t >> 1] = bv;
            }
            if (cc == 0) {
                g_as1[n * 8 + hh] = vs;
                g_ad1[n * 8 + hh] = vd;
            }
        }
    }
}

// ---------------- CSR offsets: single-kernel decoupled-lookback scan ----------------
// 196 blocks x 512 threads: all resident simultaneously (<= 592 slots), so
// spinning on predecessor flags cannot deadlock.
__global__ void __launch_bounds__(512) k_csr(int N, int nb) {
    __shared__ int s[512];
    __shared__ int s_excl;
    int t = threadIdx.x;
    int b = blockIdx.x;
    int i = b * 512 + t;
    int v = (i < N) ? g_deg[i] + 1 : 0;
    s[t] = v;
    __syncthreads();
    for (int off = 1; off < 512; off <<= 1) {
        int x = (t >= off) ? s[t - off] : 0;
        __syncthreads();
        s[t] += x;
        __syncthreads();
    }
    int incl = s[t];
    int total = s[511];

    if (t == 0) {
        if (b == 0) {
            g_prefval[0] = total;
            __threadfence();
            g_flag[0] = 2;
            s_excl = 0;
            if (nb == 1) g_rs[N] = total;
        } else {
            g_aggval[b] = total;
            __threadfence();
            g_flag[b] = 1;
            // lookback
            int run = 0;
            int p = b - 1;
            while (true) {
                int f;
                while ((f = g_flag[p]) == 0) { }
                if (f == 2) { run += g_prefval[p]; break; }
                run += g_aggval[p];
                p--;
            }
            g_prefval[b] = run + total;
            __threadfence();
            g_flag[b] = 2;
            s_excl = run;
            if (b == nb - 1) g_rs[N] = run + total;
        }
    }
    __syncthreads();
    int excl = s_excl + incl - v;
    if (i < N) {
        g_rs[i] = excl;
        g_cur[i] = excl + 1;   // slot 0 = self loop
        g_esrc[excl] = i;
        g_deg[i] = 0;          // reset for next call
    }
}

// ---------------- scatter (4-wide) + lookback flag reset ----------------
__global__ void k_scatter(const int* __restrict__ src, const int* __restrict__ dst, int E) {
    if (blockIdx.x == 0 && threadIdx.x < 256) g_flag[threadIdx.x] = 0;
    int base = (blockIdx.x * blockDim.x + threadIdx.x) * 4;
    if (base + 3 < E) {
        int4 s4 = *(const int4*)(src + base);
        int4 d4 = *(const int4*)(dst + base);
        int p0 = atomicAdd(&g_cur[d4.x], 1);
        int p1 = atomicAdd(&g_cur[d4.y], 1);
        int p2 = atomicAdd(&g_cur[d4.z], 1);
        int p3 = atomicAdd(&g_cur[d4.w], 1);
        g_esrc[p0] = s4.x;
        g_esrc[p1] = s4.y;
        g_esrc[p2] = s4.z;
        g_esrc[p3] = s4.w;
    } else {
        for (int e = base; e < E; e++) {
            int p = atomicAdd(&g_cur[dst[e]], 1);
            g_esrc[p] = src[e];
        }
    }
}

// ------- layer-1 gather (bf16, MLP=4) + softmax + lrelu + fused GEMM2 (smem) -------
__global__ void __launch_bounds__(256) k_gather1(const float* __restrict__ b1,
                                                 const float* __restrict__ W2,
                                                 const float* __restrict__ a2s,
                                                 const float* __restrict__ a2d,
                                                 int N) {
    __shared__ float W2s[128 * 16];
    __shared__ float hbs[8][132];
    int t = threadIdx.x;
    for (int i = t; i < 2048; i += 256) W2s[i] = W2[i];
    __syncthreads();

    int wib = t >> 5;
    int warp = blockIdx.x * 8 + wib;
    if (warp >= N) return;
    int n = warp;
    int l = t & 31;
    int h = l >> 2;
    int beg = g_rs[n];
    int end = g_rs[n + 1];
    float adh = g_ad1[n * 8 + h];

    const uint2* h1p = (const uint2*)g_h1b;
    float4 acc = make_float4(0.f, 0.f, 0.f, 0.f);
    float ds = 0.f;

    int i = beg;
    for (; i + 4 <= end; i += 4) {
        int s0 = g_esrc[i + 0];
        int s1 = g_esrc[i + 1];
        int s2 = g_esrc[i + 2];
        int s3 = g_esrc[i + 3];
        float a0 = g_as1[s0 * 8 + h];
        float a1 = g_as1[s1 * 8 + h];
        float a2 = g_as1[s2 * 8 + h];
        float a3 = g_as1[s3 * 8 + h];
        uint2 v0 = h1p[(size_t)s0 * 32 + l];
        uint2 v1 = h1p[(size_t)s1 * 32 + l];
        uint2 v2 = h1p[(size_t)s2 * 32 + l];
        uint2 v3 = h1p[(size_t)s3 * 32 + l];
        float e0 = a0 + adh; e0 = (e0 > 0.f) ? e0 : NEG_ATT * e0;
        float e1 = a1 + adh; e1 = (e1 > 0.f) ? e1 : NEG_ATT * e1;
        float e2 = a2 + adh; e2 = (e2 > 0.f) ? e2 : NEG_ATT * e2;
        float e3 = a3 + adh; e3 = (e3 > 0.f) ? e3 : NEG_ATT * e3;
        float x0 = __expf(e0), x1 = __expf(e1), x2 = __expf(e2), x3 = __expf(e3);
        ds += (x0 + x1) + (x2 + x3);
        {
            float2 f0 = __bfloat1622float2(*(const __nv_bfloat162*)&v0.x);
            float2 f1 = __bfloat1622float2(*(const __nv_bfloat162*)&v0.y);
            acc.x = fmaf(f0.x, x0, acc.x); acc.y = fmaf(f0.y, x0, acc.y);
            acc.z = fmaf(f1.x, x0, acc.z); acc.w = fmaf(f1.y, x0, acc.w);
        }
        {
            float2 f0 = __bfloat1622float2(*(const __nv_bfloat162*)&v1.x);
            float2 f1 = __bfloat1622float2(*(const __nv_bfloat162*)&v1.y);
            acc.x = fmaf(f0.x, x1, acc.x); acc.y = fmaf(f0.y, x1, acc.y);
            acc.z = fmaf(f1.x, x1, acc.z); acc.w = fmaf(f1.y, x1, acc.w);
        }
        {
            float2 f0 = __bfloat1622float2(*(const __nv_bfloat162*)&v2.x);
            float2 f1 = __bfloat1622float2(*(const __nv_bfloat162*)&v2.y);
            acc.x = fmaf(f0.x, x2, acc.x); acc.y = fmaf(f0.y, x2, acc.y);
            acc.z = fmaf(f1.x, x2, acc.z); acc.w = fmaf(f1.y, x2, acc.w);
        }
        {
            float2 f0 = __bfloat1622float2(*(const __nv_bfloat162*)&v3.x);
            float2 f1 = __bfloat1622float2(*(const __nv_bfloat162*)&v3.y);
            acc.x = fmaf(f0.x, x3, acc.x); acc.y = fmaf(f0.y, x3, acc.y);
            acc.z = fmaf(f1.x, x3, acc.z); acc.w = fmaf(f1.y, x3, acc.w);
        }
    }
    for (; i < end; i++) {
        int s = g_esrc[i];
        float a = g_as1[s * 8 + h];
        uint2 hv = h1p[(size_t)s * 32 + l];
        float e = a + adh;
        e = (e > 0.f) ? e : NEG_ATT * e;
        float ex = __expf(e);
        float2 f0 = __bfloat1622float2(*(const __nv_bfloat162*)&hv.x);
        float2 f1 = __bfloat1622float2(*(const __nv_bfloat162*)&hv.y);
        acc.x = fmaf(f0.x, ex, acc.x);
        acc.y = fmaf(f0.y, ex, acc.y);
        acc.z = fmaf(f1.x, ex, acc.z);
        acc.w = fmaf(f1.y, ex, acc.w);
        ds += ex;
    }

    float inv = 1.f / ds;
    float4 bb = ((const float4*)b1)[l];
    float4 o;
    o.x = acc.x * inv + bb.x;
    o.y = acc.y * inv + bb.y;
    o.z = acc.z * inv + bb.z;
    o.w = acc.w * inv + bb.w;
    o.x = (o.x > 0.f) ? o.x : NEG_ACT * o.x;
    o.y = (o.y > 0.f) ? o.y : NEG_ACT * o.y;
    o.z = (o.z > 0.f) ? o.z : NEG_ACT * o.z;
    o.w = (o.w > 0.f) ? o.w : NEG_ACT * o.w;

    hbs[wib][4 * l + 0] = o.x;
    hbs[wib][4 * l + 1] = o.y;
    hbs[wib][4 * l + 2] = o.z;
    hbs[wib][4 * l + 3] = o.w;
    __syncwarp();

    int c = l & 15;
    int half = l >> 4;
    const float* hrow = hbs[wib] + half * 64;
    float g2 = 0.f;
#pragma unroll
    for (int k4 = 0; k4 < 16; k4++) {
        int k = half * 64 + k4 * 4;
        float h0 = hrow[k4 * 4 + 0];
        float h1 = hrow[k4 * 4 + 1];
        float h2 = hrow[k4 * 4 + 2];
        float h3 = hrow[k4 * 4 + 3];
        g2 = fmaf(h0, W2s[(k + 0) * 16 + c], g2);
        g2 = fmaf(h1, W2s[(k + 1) * 16 + c], g2);
        g2 = fmaf(h2, W2s[(k + 2) * 16 + c], g2);
        g2 = fmaf(h3, W2s[(k + 3) * 16 + c], g2);
    }
    g2 += __shfl_xor_sync(0xFFFFFFFFu, g2, 16);
    if (half == 0) g_h2[n * 16 + c] = g2;

    float vs = g2 * __ldg(&a2s[c]);
    float vd = g2 * __ldg(&a2d[c]);
#pragma unroll
    for (int off = 8; off; off >>= 1) {
        vs += __shfl_xor_sync(0xFFFFFFFFu, vs, off);
        vd += __shfl_xor_sync(0xFFFFFFFFu, vd, off);
    }
    if (l == 0) { g_as2[n] = vs; g_ad2[n] = vd; }
}

// ---------------- layer-2 gather + final softmax (MLP=4 per half-warp) ----------------
__global__ void __launch_bounds__(256) k_gather2(const float* __restrict__ b2,
                                                 float* __restrict__ out, int N) {
    int warp = blockIdx.x * 8 + (threadIdx.x >> 5);
    if (warp >= N) return;
    int n = warp;
    int l = threadIdx.x & 31;
    int c = l & 15;
    int half = l >> 4;
    int beg = g_rs[n];
    int cnt = g_rs[n + 1] - beg;
    float ad = g_ad2[n];

    float acc = 0.f, ds = 0.f;
    int j = half;
    for (; j + 6 < cnt; j += 8) {
        int s0 = g_esrc[beg + j + 0];
        int s1 = g_esrc[beg + j + 2];
        int s2 = g_esrc[beg + j + 4];
        int s3 = g_esrc[beg + j + 6];
        float e0 = g_as2[s0] + ad; e0 = (e0 > 0.f) ? e0 : NEG_ATT * e0;
        float e1 = g_as2[s1] + ad; e1 = (e1 > 0.f) ? e1 : NEG_ATT * e1;
        float e2 = g_as2[s2] + ad; e2 = (e2 > 0.f) ? e2 : NEG_ATT * e2;
        float e3 = g_as2[s3] + ad; e3 = (e3 > 0.f) ? e3 : NEG_ATT * e3;
        float h0 = g_h2[s0 * 16 + c];
        float h1 = g_h2[s1 * 16 + c];
        float h2 = g_h2[s2 * 16 + c];
        float h3 = g_h2[s3 * 16 + c];
        float x0 = __expf(e0), x1 = __expf(e1), x2 = __expf(e2), x3 = __expf(e3);
        ds += (x0 + x1) + (x2 + x3);
        acc = fmaf(h0, x0, acc);
        acc = fmaf(h1, x1, acc);
        acc = fmaf(h2, x2, acc);
        acc = fmaf(h3, x3, acc);
    }
    for (; j < cnt; j += 2) {
        int s = g_esrc[beg + j];
        float e = g_as2[s] + ad;
        e = (e > 0.f) ? e : NEG_ATT * e;
        float ex = __expf(e);
        float hv = g_h2[s * 16 + c];
        acc = fmaf(hv, ex, acc);
        ds += ex;
    }
    acc += __shfl_xor_sync(0xFFFFFFFFu, acc, 16);
    ds += __shfl_xor_sync(0xFFFFFFFFu, ds, 16);

    float o = acc / ds + __ldg(&b2[c]);
    float m = o;
#pragma unroll
    for (int off = 8; off; off >>= 1) m = fmaxf(m, __shfl_xor_sync(0xFFFFFFFFu, m, off));
    float ex = __expf(o - m);
    float sm = ex;
#pragma unroll
    for (int off = 8; off; off >>= 1) sm += __shfl_xor_sync(0xFFFFFFFFu, sm, off);
    if (l < 16) out[(size_t)n * 16 + c] = ex / sm;
}

// ---------------- launch ----------------
extern "C" void kernel_launch(void* const* d_in, const int* in_sizes, int n_in,
                              void* d_out, int out_size) {
    const float* x   = (const float*)d_in[0];
    const int*   ei  = (const int*)d_in[1];
    const float* W1  = (const float*)d_in[2];
    const float* a1s = (const float*)d_in[3];
    const float* a1d = (const float*)d_in[4];
    const float* b1  = (const float*)d_in[5];
    const float* W2  = (const float*)d_in[6];
    const float* a2s = (const float*)d_in[7];
    const float* a2d = (const float*)d_in[8];
    const float* b2  = (const float*)d_in[9];
    float* out = (float*)d_out;

    int N = in_sizes[0] / 128;
    int E = in_sizes[1] / 2;
    const int* src = ei;
    const int* dst = ei + E;

    int nbScan = (N + 511) / 512;
    int GB = (N + 31) / 32;

    k_fat<<<GB + HIST_B, 128>>>(x, W1, a1s, a1d, dst, N, E, GB);      // 0
    k_csr<<<nbScan, 512>>>(N, nbScan);                                 // 1
    k_scatter<<<(E / 4 + 255) / 256, 256>>>(src, dst, E);              // 2
    k_gather1<<<(N + 7) / 8, 256>>>(b1, W2, a2s, a2d, N);              // 3 (profiled)
    k_gather2<<<(N + 7) / 8, 256>>>(b2, out, N);                       // 4
}

// round 9
// speedup vs baseline: 1.0239x; 1.0239x over previous
#include <cuda_runtime.h>
#include <cuda_bf16.h>
#include <math.h>

#define MAXN 100000
#define MAXE 1600000
#define MAXET (MAXN + MAXE)

#define NEG_ATT 0.2f
#define NEG_ACT 0.01f

// ---------------- scratch ----------------
__device__ __nv_bfloat16 g_h1b[MAXN * 128];
__device__ float g_as1[MAXN * 8];
__device__ float g_ad1[MAXN * 8];
__device__ float g_h2[MAXN * 16];
__device__ float g_as2[MAXN];
__device__ float g_ad2[MAXN];
__device__ int   g_deg[MAXN];      // zero at load; re-zeroed by k_csr each call
__device__ int   g_rs[MAXN + 1];
__device__ int   g_cur[MAXN];
__device__ int   g_esrc[MAXET];
// decoupled-lookback state (zero at load; reset by k_scatter each call)
__device__ volatile int g_flag[256];
__device__ int g_aggval[256];
__device__ int g_prefval[256];

// ---------------- f32x2 helpers ----------------
__device__ __forceinline__ unsigned long long ffma2(unsigned long long a,
                                                    unsigned long long b,
                                                    unsigned long long c) {
    unsigned long long d;
    asm("fma.rn.f32x2 %0, %1, %2, %3;" : "=l"(d) : "l"(a), "l"(b), "l"(c));
    return d;
}
__device__ __forceinline__ unsigned long long pack2(float a, float b) {
    unsigned long long r;
    asm("mov.b64 %0, {%1, %2};" : "=l"(r) : "f"(a), "f"(b));
    return r;
}
__device__ __forceinline__ float2 unpack2(unsigned long long v) {
    float2 r;
    asm("mov.b64 {%0, %1}, %2;" : "=f"(r.x), "=f"(r.y) : "l"(v));
    return r;
}

// ---------------- fat kernel: GEMM1 (FFMA2) + fused alpha1  ||  hist ----------------
#define HIST_B 512
__global__ void k_fat(const float* __restrict__ x, const float* __restrict__ W,
                      const float* __restrict__ a1s, const float* __restrict__ a1d,
                      const int* __restrict__ dst, int N, int E, int GB) {
    if (blockIdx.x >= GB) {
        int b = blockIdx.x - GB;
        for (int e = b * 128 + threadIdx.x; e < E; e += 128 * HIST_B)
            atomicAdd(&g_deg[dst[e]], 1);
        return;
    }
    __shared__ float xs[32 * 128];
    int t = threadIdx.x;
    int n0 = blockIdx.x * 32;
    const float4* x4 = (const float4*)x;
    float4* xs4 = (float4*)xs;
    for (int i = t; i < 32 * 32; i += 128) {
        int row = i >> 5, c4 = i & 31;
        float4 v = make_float4(0.f, 0.f, 0.f, 0.f);
        if (n0 + row < N) v = x4[(size_t)(n0 + row) * 32 + c4];
        xs4[i] = v;
    }
    __syncthreads();

    unsigned long long acc2[32];
#pragma unroll
    for (int i = 0; i < 32; i++) acc2[i] = 0ULL;

    const ulonglong2* xsp = (const ulonglong2*)xs;
    for (int kq = 0; kq < 32; kq++) {
        int k = kq * 4;
        float w0 = __ldg(&W[(k + 0) * 128 + t]);
        float w1 = __ldg(&W[(k + 1) * 128 + t]);
        float w2 = __ldg(&W[(k + 2) * 128 + t]);
        float w3 = __ldg(&W[(k + 3) * 128 + t]);
        unsigned long long wp0 = pack2(w0, w1);
        unsigned long long wp1 = pack2(w2, w3);
#pragma unroll
        for (int nl = 0; nl < 32; nl++) {
            ulonglong2 xv = xsp[nl * 32 + kq];
            acc2[nl] = ffma2(xv.x, wp0, acc2[nl]);
            acc2[nl] = ffma2(xv.y, wp1, acc2[nl]);
        }
    }

    float asv = __ldg(&a1s[t]);
    float adv = __ldg(&a1d[t]);
    int hh = t >> 4;
    int cc = t & 15;
    int l = t & 31;
#pragma unroll
    for (int nl = 0; nl < 32; nl++) {
        float2 p = unpack2(acc2[nl]);
        float h = p.x + p.y;
        float vs = h * asv;
        float vd = h * adv;
#pragma unroll
        for (int off = 8; off; off >>= 1) {
            vs += __shfl_xor_sync(0xFFFFFFFFu, vs, off);
            vd += __shfl_xor_sync(0xFFFFFFFFu, vd, off);
        }
        float hn = __shfl_down_sync(0xFFFFFFFFu, h, 1);
        int n = n0 + nl;
        if (n < N) {
            if ((l & 1) == 0) {
                __nv_bfloat162 bv = __floats2bfloat162_rn(h, hn);
                ((__nv_bfloat162*)(g_h1b + (size_t)n * 128))[t >> 1] = bv;
            }
            if (cc == 0) {
                g_as1[n * 8 + hh] = vs;
                g_ad1[n * 8 + hh] = vd;
            }
        }
    }
}

// ---------------- CSR offsets: decoupled lookback with WARP-PARALLEL window ----------------
__global__ void __launch_bounds__(512) k_csr(int N, int nb) {
    __shared__ int s[512];
    __shared__ int s_excl;
    int t = threadIdx.x;
    int b = blockIdx.x;
    int i = b * 512 + t;
    int v = (i < N) ? g_deg[i] + 1 : 0;
    s[t] = v;
    __syncthreads();
    for (int off = 1; off < 512; off <<= 1) {
        int x = (t >= off) ? s[t - off] : 0;
        __syncthreads();
        s[t] += x;
        __syncthreads();
    }
    int incl = s[t];
    int total = s[511];

    if (t < 32) {
        if (b == 0) {
            if (t == 0) {
                g_prefval[0] = total;
                __threadfence();
                g_flag[0] = 2;
                s_excl = 0;
                if (nb == 1) g_rs[N] = total;
            }
        } else {
            if (t == 0) {
                g_aggval[b] = total;
                __threadfence();
                g_flag[b] = 1;
            }
            __syncwarp();
            int run = 0;
            int hi = b;           // exclusive upper bound of unseen predecessors
            while (true) {
                int p = hi - 32 + t;
                int f = 2, val = 0;
                if (p >= 0) {
                    do { f = g_flag[p]; } while (f == 0);
                    val = (f == 2) ? g_prefval[p] : g_aggval[p];
                }
                unsigned m = __ballot_sync(0xFFFFFFFFu, f == 2);
                if (m) {
                    int lead = 31 - __clz(m);   // highest lane holding a full prefix
                    int contrib = (t >= lead) ? val : 0;
                    run += __reduce_add_sync(0xFFFFFFFFu, contrib);
                    break;
                } else {
                    run += __reduce_add_sync(0xFFFFFFFFu, val);
                    hi -= 32;
                }
            }
            if (t == 0) {
                g_prefval[b] = run + total;
                __threadfence();
                g_flag[b] = 2;
                s_excl = run;
                if (b == nb - 1) g_rs[N] = run + total;
            }
        }
    }
    __syncthreads();
    int excl = s_excl + incl - v;
    if (i < N) {
        g_rs[i] = excl;
        g_cur[i] = excl + 1;   // slot 0 = self loop
        g_esrc[excl] = i;
        g_deg[i] = 0;          // reset for next call
    }
}

// ---------------- scatter (4-wide) + lookback flag reset ----------------
__global__ void k_scatter(const int* __restrict__ src, const int* __restrict__ dst, int E) {
    if (blockIdx.x == 0 && threadIdx.x < 256) g_flag[threadIdx.x] = 0;
    int base = (blockIdx.x * blockDim.x + threadIdx.x) * 4;
    if (base + 3 < E) {
        int4 s4 = *(const int4*)(src + base);
        int4 d4 = *(const int4*)(dst + base);
        int p0 = atomicAdd(&g_cur[d4.x], 1);
        int p1 = atomicAdd(&g_cur[d4.y], 1);
        int p2 = atomicAdd(&g_cur[d4.z], 1);
        int p3 = atomicAdd(&g_cur[d4.w], 1);
        g_esrc[p0] = s4.x;
        g_esrc[p1] = s4.y;
        g_esrc[p2] = s4.z;
        g_esrc[p3] = s4.w;
    } else {
        for (int e = base; e < E; e++) {
            int p = atomicAdd(&g_cur[dst[e]], 1);
            g_esrc[p] = src[e];
        }
    }
}

// ------- layer-1 gather: 2 edges/warp (16 lanes each, uint4 rows) + fused GEMM2 -------
__device__ __forceinline__ void accum8(float* acc, uint4 v, float x) {
    float2 f;
    f = __bfloat1622float2(*(const __nv_bfloat162*)&v.x);
    acc[0] = fmaf(f.x, x, acc[0]); acc[1] = fmaf(f.y, x, acc[1]);
    f = __bfloat1622float2(*(const __nv_bfloat162*)&v.y);
    acc[2] = fmaf(f.x, x, acc[2]); acc[3] = fmaf(f.y, x, acc[3]);
    f = __bfloat1622float2(*(const __nv_bfloat162*)&v.z);
    acc[4] = fmaf(f.x, x, acc[4]); acc[5] = fmaf(f.y, x, acc[5]);
    f = __bfloat1622float2(*(const __nv_bfloat162*)&v.w);
    acc[6] = fmaf(f.x, x, acc[6]); acc[7] = fmaf(f.y, x, acc[7]);
}

__global__ void __launch_bounds__(256) k_gather1(const float* __restrict__ b1,
                                                 const float* __restrict__ W2,
                                                 const float* __restrict__ a2s,
                                                 const float* __restrict__ a2d,
                                                 int N) {
    __shared__ float W2s[128 * 16];
    __shared__ float hbs[8][132];
    int t = threadIdx.x;
    for (int i = t; i < 2048; i += 256) W2s[i] = W2[i];
    __syncthreads();

    int wib = t >> 5;
    int warp = blockIdx.x * 8 + wib;
    if (warp >= N) return;
    int n = warp;
    int l = t & 31;
    int half = l >> 4;        // which edge of the pair this lane works on
    int li = l & 15;          // 8-column block within the row (cols 8*li..8*li+7)
    int h = li >> 1;          // head owning those columns
    int beg = g_rs[n];
    int end = g_rs[n + 1];
    float adh = g_ad1[n * 8 + h];

    const uint4* h1p = (const uint4*)g_h1b;   // row = 16 uint4
    float acc[8];
#pragma unroll
    for (int k = 0; k < 8; k++) acc[k] = 0.f;
    float ds = 0.f;

    int i = beg;
    for (; i + 4 <= end; i += 4) {
        int s0 = g_esrc[i + half];
        int s1 = g_esrc[i + 2 + half];
        float a0 = g_as1[s0 * 8 + h];
        float a1 = g_as1[s1 * 8 + h];
        uint4 v0 = h1p[s0 * 16 + li];
        uint4 v1 = h1p[s1 * 16 + li];
        float e0 = a0 + adh; e0 = (e0 > 0.f) ? e0 : NEG_ATT * e0;
        float e1 = a1 + adh; e1 = (e1 > 0.f) ? e1 : NEG_ATT * e1;
        float x0 = __expf(e0), x1 = __expf(e1);
        ds += x0 + x1;
        accum8(acc, v0, x0);
        accum8(acc, v1, x1);
    }
    // tail (0..3 edges): half0 covers i, i+2; half1 covers i+1
    if (i + half < end) {
        int s = g_esrc[i + half];
        float a = g_as1[s * 8 + h];
        uint4 v = h1p[s * 16 + li];
        float e = a + adh; e = (e > 0.f) ? e : NEG_ATT * e;
        float x = __expf(e);
        ds += x;
        accum8(acc, v, x);
    }
    if (i + 2 + half < end) {
        int s = g_esrc[i + 2 + half];
        float a = g_as1[s * 8 + h];
        uint4 v = h1p[s * 16 + li];
        float e = a + adh; e = (e > 0.f) ? e : NEG_ATT * e;
        float x = __expf(e);
        ds += x;
        accum8(acc, v, x);
    }

    // combine the two half-warp partial sums
#pragma unroll
    for (int k = 0; k < 8; k++) acc[k] += __shfl_xor_sync(0xFFFFFFFFu, acc[k], 16);
    ds += __shfl_xor_sync(0xFFFFFFFFu, ds, 16);

    float inv = 1.f / ds;
    float4 bb0 = ((const float4*)b1)[2 * li];
    float4 bb1 = ((const float4*)b1)[2 * li + 1];
    float o[8];
    o[0] = acc[0] * inv + bb0.x;
    o[1] = acc[1] * inv + bb0.y;
    o[2] = acc[2] * inv + bb0.z;
    o[3] = acc[3] * inv + bb0.w;
    o[4] = acc[4] * inv + bb1.x;
    o[5] = acc[5] * inv + bb1.y;
    o[6] = acc[6] * inv + bb1.z;
    o[7] = acc[7] * inv + bb1.w;
#pragma unroll
    for (int k = 0; k < 8; k++) o[k] = (o[k] > 0.f) ? o[k] : NEG_ACT * o[k];

    // stage hb row (both halves write identical values; benign)
#pragma unroll
    for (int k = 0; k < 8; k++) hbs[wib][8 * li + k] = o[k];
    __syncwarp();

    // fused GEMM2: lane (c = l&15, half) accumulates over its 64 k values
    int c = l & 15;
    const float* hrow = hbs[wib] + half * 64;
    float g2 = 0.f;
#pragma unroll
    for (int k4 = 0; k4 < 16; k4++) {
        int k = half * 64 + k4 * 4;
        float h0 = hrow[k4 * 4 + 0];
        float h1 = hrow[k4 * 4 + 1];
        float h2 = hrow[k4 * 4 + 2];
        float h3 = hrow[k4 * 4 + 3];
        g2 = fmaf(h0, W2s[(k + 0) * 16 + c], g2);
        g2 = fmaf(h1, W2s[(k + 1) * 16 + c], g2);
        g2 = fmaf(h2, W2s[(k + 2) * 16 + c], g2);
        g2 = fmaf(h3, W2s[(k + 3) * 16 + c], g2);
    }
    g2 += __shfl_xor_sync(0xFFFFFFFFu, g2, 16);
    if (half == 0) g_h2[n * 16 + c] = g2;

    float vs = g2 * __ldg(&a2s[c]);
    float vd = g2 * __ldg(&a2d[c]);
#pragma unroll
    for (int off = 8; off; off >>= 1) {
        vs += __shfl_xor_sync(0xFFFFFFFFu, vs, off);
        vd += __shfl_xor_sync(0xFFFFFFFFu, vd, off);
    }
    if (l == 0) { g_as2[n] = vs; g_ad2[n] = vd; }
}

// ---------------- layer-2 gather + final softmax (MLP=4 per half-warp) ----------------
__global__ void __launch_bounds__(256) k_gather2(const float* __restrict__ b2,
                                                 float* __restrict__ out, int N) {
    int warp = blockIdx.x * 8 + (threadIdx.x >> 5);
    if (warp >= N) return;
    int n = warp;
    int l = threadIdx.x & 31;
    int c = l & 15;
    int half = l >> 4;
    int beg = g_rs[n];
    int cnt = g_rs[n + 1] - beg;
    float ad = g_ad2[n];

    float acc = 0.f, ds = 0.f;
    int j = half;
    for (; j + 6 < cnt; j += 8) {
        int s0 = g_esrc[beg + j + 0];
        int s1 = g_esrc[beg + j + 2];
        int s2 = g_esrc[beg + j + 4];
        int s3 = g_esrc[beg + j + 6];
        float e0 = g_as2[s0] + ad; e0 = (e0 > 0.f) ? e0 : NEG_ATT * e0;
        float e1 = g_as2[s1] + ad; e1 = (e1 > 0.f) ? e1 : NEG_ATT * e1;
        float e2 = g_as2[s2] + ad; e2 = (e2 > 0.f) ? e2 : NEG_ATT * e2;
        float e3 = g_as2[s3] + ad; e3 = (e3 > 0.f) ? e3 : NEG_ATT * e3;
        float h0 = g_h2[s0 * 16 + c];
        float h1 = g_h2[s1 * 16 + c];
        float h2 = g_h2[s2 * 16 + c];
        float h3 = g_h2[s3 * 16 + c];
        float x0 = __expf(e0), x1 = __expf(e1), x2 = __expf(e2), x3 = __expf(e3);
        ds += (x0 + x1) + (x2 + x3);
        acc = fmaf(h0, x0, acc);
        acc = fmaf(h1, x1, acc);
        acc = fmaf(h2, x2, acc);
        acc = fmaf(h3, x3, acc);
    }
    for (; j < cnt; j += 2) {
        int s = g_esrc[beg + j];
        float e = g_as2[s] + ad;
        e = (e > 0.f) ? e : NEG_ATT * e;
        float ex = __expf(e);
        float hv = g_h2[s * 16 + c];
        acc = fmaf(hv, ex, acc);
        ds += ex;
    }
    acc += __shfl_xor_sync(0xFFFFFFFFu, acc, 16);
    ds += __shfl_xor_sync(0xFFFFFFFFu, ds, 16);

    float o = acc / ds + __ldg(&b2[c]);
    float m = o;
#pragma unroll
    for (int off = 8; off; off >>= 1) m = fmaxf(m, __shfl_xor_sync(0xFFFFFFFFu, m, off));
    float ex = __expf(o - m);
    float sm = ex;
#pragma unroll
    for (int off = 8; off; off >>= 1) sm += __shfl_xor_sync(0xFFFFFFFFu, sm, off);
    if (l < 16) out[(size_t)n * 16 + c] = ex / sm;
}

// ---------------- launch ----------------
extern "C" void kernel_launch(void* const* d_in, const int* in_sizes, int n_in,
                              void* d_out, int out_size) {
    const float* x   = (const float*)d_in[0];
    const int*   ei  = (const int*)d_in[1];
    const float* W1  = (const float*)d_in[2];
    const float* a1s = (const float*)d_in[3];
    const float* a1d = (const float*)d_in[4];
    const float* b1  = (const float*)d_in[5];
    const float* W2  = (const float*)d_in[6];
    const float* a2s = (const float*)d_in[7];
    const float* a2d = (const float*)d_in[8];
    const float* b2  = (const float*)d_in[9];
    float* out = (float*)d_out;

    int N = in_sizes[0] / 128;
    int E = in_sizes[1] / 2;
    const int* src = ei;
    const int* dst = ei + E;

    int nbScan = (N + 511) / 512;
    int GB = (N + 31) / 32;

    k_fat<<<GB + HIST_B, 128>>>(x, W1, a1s, a1d, dst, N, E, GB);      // 0
    k_csr<<<nbScan, 512>>>(N, nbScan);                                 // 1
    k_scatter<<<(E / 4 + 255) / 256, 256>>>(src, dst, E);              // 2
    k_gather1<<<(N + 7) / 8, 256>>>(b1, W2, a2s, a2d, N);              // 3 (profiled)
    k_gather2<<<(N + 7) / 8, 256>>>(b2, out, N);                       // 4
}